// round 9
// baseline (speedup 1.0000x reference)
#include <cuda_runtime.h>
#include <cstdint>

#define BB 8
#define CC 32
#define FF 8
#define HH 128
#define WW 128
#define IHP 129
#define IWP 132                        // padded row stride (floats), 528 B
typedef unsigned long long ull;

#define A_SMEM_FLOATS (IHP*IWP)        // 68112 B -> 3 blocks/SM

// Global integral scratch: (256, 129, 132) f32 = 17.4 MB (L2-resident)
__device__ __align__(256) float g_I[BB * CC * IHP * IWP];

__device__ __forceinline__ ull pk2(float lo, float hi) {
    ull r; asm("mov.b64 %0, {%1, %2};" : "=l"(r) : "f"(lo), "f"(hi)); return r;
}
__device__ __forceinline__ ull ffma2(ull a, ull b, ull c) {
    ull r; asm("fma.rn.f32x2 %0, %1, %2, %3;" : "=l"(r) : "l"(a), "l"(b), "l"(c));
    return r;
}
__device__ __forceinline__ uint32_t smem_u32(const void* p) {
    uint32_t a;
    asm("{ .reg .u64 t; cvta.to.shared.u64 t, %1; cvt.u32.u64 %0, t; }"
        : "=r"(a) : "l"(p));
    return a;
}

// ---------------------------------------------------------------------------
// Kernel A: build padded integral image per (b,c) in smem, write to g_I.
// No stripe-offset table: per-warp register accumulation (smem = I only).
// ---------------------------------------------------------------------------
__global__ void __launch_bounds__(512) build_integral(const float* __restrict__ in)
{
    extern __shared__ float sm[];
    float* I = sm;                      // [IHP][IWP]

    const int bc   = blockIdx.x;
    const int tid  = threadIdx.x;
    const int wid  = tid >> 5;
    const int lane = tid & 31;

    if (tid < IWP) I[tid] = 0.0f;

    // ---- Row exclusive scans: warp wid -> rows 8w..8w+7 --------------------
    const float* img = in + (size_t)bc * (HH * WW);
#pragma unroll
    for (int r = 0; r < 8; ++r) {
        int row = wid * 8 + r;
        float4 cv = *(const float4*)(img + (size_t)row * WW + 4 * lane);
        float s4 = cv.x + cv.y + cv.z + cv.w;
        float x = __shfl_up_sync(0xffffffffu, s4, 1);
        if (lane == 0) x = 0.0f;
#pragma unroll
        for (int off = 1; off < 32; off <<= 1) {
            float t = __shfl_up_sync(0xffffffffu, x, off);
            if (lane >= off) x += t;
        }
        float4 o;
        o.x = x;
        o.y = x + cv.x;
        o.z = o.y + cv.y;
        o.w = o.z + cv.z;
        float* dst = I + (size_t)(row + 1) * IWP;
        *(float4*)(dst + 4 * lane) = o;
        if (lane == 31) {
            dst[128] = o.w + cv.w;
            dst[129] = 0.0f; dst[130] = 0.0f; dst[131] = 0.0f;
        }
    }
    __syncthreads();

    // ---- level 1: within-stripe inclusive sums (8-row stripes) -------------
    for (int g = lane; g < 33; g += 32) {
        float* col = I + 4 * g + (size_t)(8 * wid + 1) * IWP;
        float4 s = make_float4(0.f, 0.f, 0.f, 0.f);
#pragma unroll
        for (int r = 0; r < 8; ++r) {
            float4 v = *(float4*)(col + (size_t)r * IWP);
            s.x += v.x; s.y += v.y; s.z += v.z; s.w += v.w;
            *(float4*)(col + (size_t)r * IWP) = s;
        }
    }
    __syncthreads();

    // ---- level 2: per-warp stripe offset in REGISTERS -----------------------
    // Warp wid needs sum of stripe totals (rows 8s+8) for s < wid. Reads happen
    // before any level-3 modification (guarded by the syncthreads below).
    float4 off_a = make_float4(0.f, 0.f, 0.f, 0.f);
    float4 off_b = make_float4(0.f, 0.f, 0.f, 0.f);   // group 32 (lane 0 only)
    for (int s = 0; s < wid; ++s) {
        const float4* tr = (const float4*)(I + (size_t)(8 * s + 8) * IWP);
        float4 v = tr[lane];
        off_a.x += v.x; off_a.y += v.y; off_a.z += v.z; off_a.w += v.w;
        if (lane == 0) {
            float4 v2 = tr[32];
            off_b.x += v2.x; off_b.y += v2.y; off_b.z += v2.z; off_b.w += v2.w;
        }
    }
    __syncthreads();

    // ---- level 3: add offsets to this warp's stripe -------------------------
    {
        float* colb = I + (size_t)(8 * wid + 1) * IWP;
#pragma unroll
        for (int r = 0; r < 8; ++r) {
            float4* p = (float4*)(colb + (size_t)r * IWP) + lane;
            float4 v = *p;
            v.x += off_a.x; v.y += off_a.y; v.z += off_a.z; v.w += off_a.w;
            *p = v;
            if (lane == 0) {
                float4* p2 = (float4*)(colb + (size_t)r * IWP) + 32;
                float4 v2 = *p2;
                v2.x += off_b.x; v2.y += off_b.y; v2.z += off_b.z; v2.w += off_b.w;
                *p2 = v2;
            }
        }
    }
    __syncthreads();

    // ---- Write integral to global (coalesced float4) ------------------------
    float4* dst = (float4*)(g_I + (size_t)bc * (IHP * IWP));
    const float4* src = (const float4*)I;
    const int n4 = (IHP * IWP) / 4;
    for (int i = tid; i < n4; i += 512) dst[i] = src[i];
}

// ---------------------------------------------------------------------------
// Kernel B: block = (hchunk, bc), 8 warps = f, 16 h each. Window rows loaded
// from g_I (L1/L2 hot). Just-in-time loads + SELP advance; 4 blocks/SM.
// ---------------------------------------------------------------------------
__global__ void __launch_bounds__(256, 4) boxconv_main(
    const float* __restrict__ xmn, const float* __restrict__ xmx,
    const float* __restrict__ ymn, const float* __restrict__ ymx,
    float* __restrict__ out)
{
    __shared__ float Dsh[8][2][IWP];      // 8448 B

    const int hc   = blockIdx.x;          // 0..7
    const int bc   = blockIdx.y;
    const int tid  = threadIdx.x;
    const int wid  = tid >> 5;
    const int lane = tid & 31;
    const int f    = wid;
    const int cf   = (bc % CC) * FF + f;

    const float Wf = 128.0f;
    const float xm  = __ldg(&xmn[cf]) * 128.0f;
    const float xM1 = __ldg(&xmx[cf]) * 128.0f + 1.0f;
    const float ym  = __ldg(&ymn[cf]) * Wf;
    const float yM  = __ldg(&ymx[cf]) * Wf;
    const int icx0 = (int)floorf(xm);
    const int icx1 = (int)floorf(xM1);

    // h-invariant column-interp params + fixed gather addresses
    const uint32_t dbase = smem_u32(&Dsh[wid][0][0]);
    uint32_t ga0[4], ga1[4];
    float b0[4], b1[4];
#pragma unroll
    for (int k = 0; k < 4; ++k) {
        float wv = (float)(lane + 32 * k);
        float v0 = fminf(fmaxf(wv + ym, 0.0f), Wf);
        float v1 = fminf(fmaxf(wv + yM + 1.0f, 0.0f), Wf);
        float j0f = fminf(floorf(v0), Wf - 1.0f);
        float j1f = fminf(floorf(v1), Wf - 1.0f);
        b0[k] = v0 - j0f;
        b1[k] = v1 - j1f;
        ga0[k] = dbase + 4u * (uint32_t)(int)j0f;
        ga1[k] = dbase + 4u * (uint32_t)(int)j1f;
    }

    const float* gIbc = g_I + (size_t)bc * (IHP * IWP);
    const ull M1 = pk2(-1.0f, -1.0f);
    const uint32_t dst0 = dbase + 16u * (uint32_t)lane;
    const int h0 = hc * 16;
    float* outc = out + ((size_t)(bc * FF + f) * HH + h0) * WW + lane;

#define LOADROW_G(ROW, ra, rb, e)                                            \
    { const float* bp_ = gIbc + (size_t)(ROW) * IWP;                         \
      float4 v_ = *(const float4*)(bp_ + 4 * lane);                          \
      ra = pk2(v_.x, v_.y); rb = pk2(v_.z, v_.w);                            \
      e = __ldg(bp_ + 128); }

    // rolling window registers (rows pi0, pi0+1, pi1, pi1+1)
    ull r00a, r00b, r01a, r01b, r10a, r10b, r11a, r11b;
    float e00, e01, e10, e11;
    int pi0, pi1;

    // prologue: p rows for h0 (q rows loaded in first iteration)
    pi0 = min(max(h0 + icx0, 0), 127) - 1;   // bias so first ITER "advances"
    pi1 = min(max(h0 + icx1, 0), 127) - 1;
    LOADROW_G(pi0 + 1, r01a, r01b, e01);     // becomes p after first advance
    LOADROW_G(pi1 + 1, r11a, r11b, e11);
    r00a = r01a; r00b = r01b; e00 = e01;     // placeholders (replaced by SELP)
    r10a = r11a; r10b = r11b; e10 = e11;

#define ITER(SUB, SOFF)                                                      \
    {                                                                        \
        const int h = h0 + hh + (SUB);                                       \
        int i0 = min(max(h + icx0, 0), 127);                                 \
        int i1 = min(max(h + icx1, 0), 127);                                 \
        /* unconditional q-row loads (value-identical when not advancing) */ \
        ull nq0a, nq0b, nq1a, nq1b; float ne01, ne11;                        \
        LOADROW_G(i0 + 1, nq0a, nq0b, ne01);                                 \
        LOADROW_G(i1 + 1, nq1a, nq1b, ne11);                                 \
        bool adv0 = (i0 != pi0);                                             \
        bool adv1 = (i1 != pi1);                                             \
        r00a = adv0 ? r01a : r00a;                                           \
        r00b = adv0 ? r01b : r00b;                                           \
        e00  = adv0 ? e01  : e00;                                            \
        r10a = adv1 ? r11a : r10a;                                           \
        r10b = adv1 ? r11b : r10b;                                           \
        e10  = adv1 ? e11  : e10;                                            \
        r01a = nq0a; r01b = nq0b; e01 = ne01;                                \
        r11a = nq1a; r11b = nq1b; e11 = ne11;                                \
        pi0 = i0; pi1 = i1;                                                  \
        float u0 = fminf(fmaxf((float)h + xm, 0.0f), 128.0f);                \
        float u1 = fminf(fmaxf((float)h + xM1, 0.0f), 128.0f);               \
        float a0 = u0 - (float)i0;                                           \
        float a1 = u1 - (float)i1;                                           \
        ull a0v = pk2(a0, a0), a1v = pk2(a1, a1);                            \
        ull g0a = ffma2(a0v, ffma2(r00a, M1, r01a), r00a);                   \
        ull g0b = ffma2(a0v, ffma2(r00b, M1, r01b), r00b);                   \
        ull g1a = ffma2(a1v, ffma2(r10a, M1, r11a), r10a);                   \
        ull g1b = ffma2(a1v, ffma2(r10b, M1, r11b), r10b);                   \
        ull da = ffma2(g0a, M1, g1a);                                        \
        ull db = ffma2(g0b, M1, g1b);                                        \
        asm volatile("st.shared.v2.u64 [%0+" #SOFF "], {%1, %2};"            \
                     :: "r"(dst0), "l"(da), "l"(db) : "memory");             \
        float ge0 = fmaf(a0, e01 - e00, e00);                                \
        float ge1 = fmaf(a1, e11 - e10, e10);                                \
        if (lane == 0)                                                       \
            asm volatile("st.shared.f32 [%0+512+" #SOFF "], %1;"             \
                         :: "r"(dbase), "f"(ge1 - ge0) : "memory");          \
        __syncwarp();                                                        \
        float* orow = outc + (size_t)(hh + (SUB)) * WW;                      \
        _Pragma("unroll")                                                    \
        for (int k = 0; k < 4; ++k) {                                        \
            float d00, d01, d10, d11;                                        \
            asm volatile("ld.shared.f32 %0, [%1+" #SOFF "];"                 \
                         : "=f"(d00) : "r"(ga0[k]));                         \
            asm volatile("ld.shared.f32 %0, [%1+4+" #SOFF "];"               \
                         : "=f"(d01) : "r"(ga0[k]));                         \
            asm volatile("ld.shared.f32 %0, [%1+" #SOFF "];"                 \
                         : "=f"(d10) : "r"(ga1[k]));                         \
            asm volatile("ld.shared.f32 %0, [%1+4+" #SOFF "];"               \
                         : "=f"(d11) : "r"(ga1[k]));                         \
            float s0 = fmaf(b0[k], d01 - d00, d00);                          \
            float s1 = fmaf(b1[k], d11 - d10, d10);                          \
            orow[32 * k] = s1 - s0;                                          \
        }                                                                    \
    }

    for (int hh = 0; hh < 16; hh += 2) {
        ITER(0, 0)
        ITER(1, 528)
    }
#undef ITER
#undef LOADROW_G
}

// ---------------------------------------------------------------------------
extern "C" void kernel_launch(void* const* d_in, const int* in_sizes, int n_in,
                              void* d_out, int out_size) {
    const float* input = (const float*)d_in[0];
    const float* x_min = (const float*)d_in[1];
    const float* x_max = (const float*)d_in[2];
    const float* y_min = (const float*)d_in[3];
    const float* y_max = (const float*)d_in[4];
    float* out = (float*)d_out;

    static int configured = 0;
    const int a_smem = A_SMEM_FLOATS * sizeof(float);   // 68112 B
    if (!configured) {
        cudaFuncSetAttribute(build_integral,
                             cudaFuncAttributeMaxDynamicSharedMemorySize, a_smem);
        configured = 1;
    }

    build_integral<<<BB * CC, 512, a_smem>>>(input);

    dim3 grid(8, BB * CC);    // (h-chunk, bc) -> 2048 blocks
    boxconv_main<<<grid, 256>>>(x_min, x_max, y_min, y_max, out);
}